// round 1
// baseline (speedup 1.0000x reference)
#include <cuda_runtime.h>

// Problem constants
#define Bv 8
#define Vv 256
#define Hv 128
#define ROWS (Bv*Vv)          // 2048
#define H4 (Hv/4)             // 32 float4 per row

// Intermediates (device globals; no allocation allowed)
__device__ float g_h0[ROWS*Hv];
__device__ float g_neigh[ROWS*Hv];

__device__ __forceinline__ float silu_f(float x) {
    return x * (1.0f / (1.0f + __expf(-x)));
}

// ---------------------------------------------------------------------------
// Kernel A: h0 = silu(h @ W_pre + b_pre)
// 16 rows per block, 128 threads (one per output h). W column streamed once
// per block -> W L2 traffic = 128 blocks * 64KB = 8MB.
// ---------------------------------------------------------------------------
__global__ void __launch_bounds__(128) pre_kernel(
    const float* __restrict__ h,
    const float* __restrict__ Wpre,
    const float* __restrict__ bpre)
{
    __shared__ float hs[16][Hv];
    const int t = threadIdx.x;
    const int row0 = blockIdx.x * 16;

    const float4* h4 = (const float4*)h;
    float4* hs4 = (float4*)hs;
    for (int x = t; x < 16 * H4; x += 128)
        hs4[x] = h4[row0 * H4 + x];
    __syncthreads();

    float acc[16];
    const float bb = bpre[t];
#pragma unroll
    for (int r = 0; r < 16; r++) acc[r] = bb;

    for (int k = 0; k < Hv; k++) {
        const float w = Wpre[k * Hv + t];
#pragma unroll
        for (int r = 0; r < 16; r++)
            acc[r] = fmaf(hs[r][k], w, acc[r]);
    }

#pragma unroll
    for (int r = 0; r < 16; r++)
        g_h0[(row0 + r) * Hv + t] = silu_f(acc[r]);
}

// ---------------------------------------------------------------------------
// Kernel B (dominant): neigh[b,i,h] = max_j (graph[b,i,j] ? 0 : e[b,i,j,h]*h0[b,j,h])
// One block per (b, 8-i-tile): 256 blocks x 256 threads.
//   thread: hq = lane float4 index within H, isub = which i of the tile.
// h0 chunk (64 j x 128 h) staged in smem, shared across the 8 i rows.
// e read exactly once via coalesced LDG.128, unrolled x8 for MLP.
// ---------------------------------------------------------------------------
__global__ void __launch_bounds__(256) agg_kernel(
    const float* __restrict__ e,
    const int*   __restrict__ graph)
{
    __shared__ float4 h0s[64][H4];   // 32 KB
    __shared__ int    gsh[8][Vv];    // 8 KB

    const int tid  = threadIdx.x;
    const int hq   = tid & 31;       // float4 index in H
    const int isub = tid >> 5;       // 0..7: which i in the tile
    const int blocksPerB = Vv / 8;   // 32
    const int b  = blockIdx.x / blocksPerB;
    const int i0 = (blockIdx.x % blocksPerB) * 8;
    const int i  = i0 + isub;

    // Stage the graph mask rows for this i-tile.
    for (int x = tid; x < 8 * Vv; x += 256) {
        const int ii = x >> 8;
        const int j  = x & (Vv - 1);
        gsh[ii][j] = graph[(b * Vv + i0 + ii) * Vv + j];
    }

    const float4* E  = (const float4*)e + (size_t)(b * Vv + i) * Vv * H4 + hq;
    const float4* H0 = (const float4*)g_h0 + (size_t)b * Vv * H4;

    const float NEG_INF = __int_as_float(0xff800000);
    float4 acc = make_float4(NEG_INF, NEG_INF, NEG_INF, NEG_INF);

    for (int jc = 0; jc < Vv; jc += 64) {
        __syncthreads();   // also covers gsh on the first pass
        for (int x = tid; x < 64 * H4; x += 256) {
            const int jj = x >> 5;
            const int q  = x & 31;
            h0s[jj][q] = H0[(jc + jj) * H4 + q];
        }
        __syncthreads();

#pragma unroll 8
        for (int jj = 0; jj < 64; jj++) {
            const int j = jc + jj;
            float4 ev = E[(size_t)j * H4];
            float4 hv = h0s[jj][hq];
            if (gsh[isub][j] != 0) { hv.x = 0.f; hv.y = 0.f; hv.z = 0.f; hv.w = 0.f; }
            acc.x = fmaxf(acc.x, ev.x * hv.x);
            acc.y = fmaxf(acc.y, ev.y * hv.y);
            acc.z = fmaxf(acc.z, ev.z * hv.z);
            acc.w = fmaxf(acc.w, ev.w * hv.w);
        }
    }

    ((float4*)g_neigh)[(b * Vv + i) * H4 + hq] = acc;
}

// ---------------------------------------------------------------------------
// Kernel C: out = silu( silu(h @ W_skip + b_skip) + silu([h0,neigh] @ W_post + b_post) )
// 16 rows per block, 128 threads. W columns streamed once per block.
// ---------------------------------------------------------------------------
__global__ void __launch_bounds__(128) post_kernel(
    const float* __restrict__ h,
    const float* __restrict__ Wpost,
    const float* __restrict__ bpost,
    const float* __restrict__ Wskip,
    const float* __restrict__ bskip,
    float* __restrict__ out)
{
    __shared__ float h0s[16][Hv];
    __shared__ float nes[16][Hv];
    __shared__ float hsm[16][Hv];

    const int t = threadIdx.x;
    const int row0 = blockIdx.x * 16;

    const float4* h4 = (const float4*)h;
    for (int x = t; x < 16 * H4; x += 128) {
        ((float4*)h0s)[x] = ((const float4*)g_h0)[row0 * H4 + x];
        ((float4*)nes)[x] = ((const float4*)g_neigh)[row0 * H4 + x];
        ((float4*)hsm)[x] = h4[row0 * H4 + x];
    }
    __syncthreads();

    float accP[16], accS[16];
    const float bp = bpost[t];
    const float bs = bskip[t];
#pragma unroll
    for (int r = 0; r < 16; r++) { accP[r] = bp; accS[r] = bs; }

    for (int k = 0; k < Hv; k++) {
        const float w1 = Wpost[k * Hv + t];
        const float w2 = Wpost[(Hv + k) * Hv + t];
        const float w3 = Wskip[k * Hv + t];
#pragma unroll
        for (int r = 0; r < 16; r++) {
            accP[r] = fmaf(h0s[r][k], w1, accP[r]);
            accP[r] = fmaf(nes[r][k], w2, accP[r]);
            accS[r] = fmaf(hsm[r][k], w3, accS[r]);
        }
    }

#pragma unroll
    for (int r = 0; r < 16; r++)
        out[(row0 + r) * Hv + t] = silu_f(silu_f(accS[r]) + silu_f(accP[r]));
}

// ---------------------------------------------------------------------------
extern "C" void kernel_launch(void* const* d_in, const int* in_sizes, int n_in,
                              void* d_out, int out_size)
{
    const float* h     = (const float*)d_in[0];
    const float* e     = (const float*)d_in[1];
    const int*   graph = (const int*)  d_in[2];
    const float* Wpre  = (const float*)d_in[3];
    const float* bpre  = (const float*)d_in[4];
    const float* Wpost = (const float*)d_in[5];
    const float* bpost = (const float*)d_in[6];
    const float* Wskip = (const float*)d_in[7];
    const float* bskip = (const float*)d_in[8];
    float* out = (float*)d_out;

    pre_kernel<<<ROWS / 16, 128>>>(h, Wpre, bpre);
    agg_kernel<<<(Bv * Vv) / 8, 256>>>(e, graph);
    post_kernel<<<ROWS / 16, 128>>>(h, Wpost, bpost, Wskip, bskip, out);
}

// round 2
// speedup vs baseline: 1.1053x; 1.1053x over previous
#include <cuda_runtime.h>

// Problem constants
#define Bv 8
#define Vv 256
#define Hv 128
#define ROWS (Bv*Vv)          // 2048
#define H4 (Hv/4)             // 32 float4 per row

// Intermediates (device globals; no allocation allowed)
__device__ float g_h0[ROWS*Hv];
__device__ float g_neigh[ROWS*Hv];

__device__ __forceinline__ float silu_f(float x) {
    return x * (1.0f / (1.0f + __expf(-x)));
}

// ---------------------------------------------------------------------------
// Kernel A: h0 = silu(h @ W_pre + b_pre)
// 8 rows per block -> 256 blocks, 128 threads (one per output col).
// ---------------------------------------------------------------------------
__global__ void __launch_bounds__(128) pre_kernel(
    const float* __restrict__ h,
    const float* __restrict__ Wpre,
    const float* __restrict__ bpre)
{
    __shared__ float hs[8][Hv];
    const int t = threadIdx.x;
    const int row0 = blockIdx.x * 8;

    // 8*32 = 256 float4, 128 threads -> 2 each
    const float4* h4 = (const float4*)h;
    float4* hs4 = (float4*)hs;
    hs4[t]       = h4[row0 * H4 + t];
    hs4[t + 128] = h4[row0 * H4 + t + 128];
    __syncthreads();

    float acc[8];
    const float bb = bpre[t];
#pragma unroll
    for (int r = 0; r < 8; r++) acc[r] = bb;

#pragma unroll 8
    for (int k = 0; k < Hv; k++) {
        const float w = Wpre[k * Hv + t];
#pragma unroll
        for (int r = 0; r < 8; r++)
            acc[r] = fmaf(hs[r][k], w, acc[r]);
    }

#pragma unroll
    for (int r = 0; r < 8; r++)
        g_h0[(row0 + r) * Hv + t] = silu_f(acc[r]);
}

// ---------------------------------------------------------------------------
// Kernel B (dominant): neigh[b,i,h] = max_j (graph[b,i,j] ? 0 : e[b,i,j,h]*h0[b,j,h])
// One block per (b, 8-i-tile): 256 blocks x 256 threads, all resident.
// h0 chunk (64 j x 128 h) double-buffered through registers so the
// __syncthreads window is just an STS burst, not an L2 round-trip.
// ---------------------------------------------------------------------------
__global__ void __launch_bounds__(256) agg_kernel(
    const float* __restrict__ e,
    const int*   __restrict__ graph)
{
    __shared__ float4 h0s[64][H4];   // 32 KB
    __shared__ int    gsh[8][Vv];    // 8 KB

    const int tid  = threadIdx.x;
    const int hq   = tid & 31;       // float4 index in H
    const int isub = tid >> 5;       // 0..7: which i in the tile
    const int blocksPerB = Vv / 8;   // 32
    const int b  = blockIdx.x / blocksPerB;
    const int i0 = (blockIdx.x % blocksPerB) * 8;
    const int i  = i0 + isub;

    // Stage the graph mask rows for this i-tile.
    for (int x = tid; x < 8 * Vv; x += 256) {
        const int ii = x >> 8;
        const int j  = x & (Vv - 1);
        gsh[ii][j] = graph[(b * Vv + i0 + ii) * Vv + j];
    }

    const float4* E  = (const float4*)e + (size_t)(b * Vv + i) * Vv * H4 + hq;
    const float4* H0 = (const float4*)g_h0 + (size_t)b * Vv * H4;

    // Prefetch chunk 0 of h0 into registers: 64*32 float4 / 256 thr = 8 each.
    // Layout x = r*256 + tid for coalesced LDG.
    float4 pf[8];
#pragma unroll
    for (int r = 0; r < 8; r++) {
        const int x = r * 256 + tid;
        pf[r] = H0[x];                  // (x>>5) = jj, (x&31) = q; chunk 0
    }

    const float NEG_INF = __int_as_float(0xff800000);
    float4 acc = make_float4(NEG_INF, NEG_INF, NEG_INF, NEG_INF);

#pragma unroll
    for (int jc = 0; jc < Vv; jc += 64) {
        __syncthreads();                 // buffer free (covers gsh 1st pass)
#pragma unroll
        for (int r = 0; r < 8; r++) {
            const int x = r * 256 + tid;
            h0s[x >> 5][x & 31] = pf[r];
        }
        __syncthreads();

        // Prefetch next chunk while computing this one.
        if (jc + 64 < Vv) {
#pragma unroll
            for (int r = 0; r < 8; r++) {
                const int x = r * 256 + tid;
                pf[r] = H0[(jc + 64) * H4 + x];
            }
        }

#pragma unroll 8
        for (int jj = 0; jj < 64; jj++) {
            const int j = jc + jj;
            float4 ev = E[(size_t)j * H4];
            float4 hv = h0s[jj][hq];
            if (gsh[isub][j] != 0) { hv.x = 0.f; hv.y = 0.f; hv.z = 0.f; hv.w = 0.f; }
            acc.x = fmaxf(acc.x, ev.x * hv.x);
            acc.y = fmaxf(acc.y, ev.y * hv.y);
            acc.z = fmaxf(acc.z, ev.z * hv.z);
            acc.w = fmaxf(acc.w, ev.w * hv.w);
        }
    }

    ((float4*)g_neigh)[(b * Vv + i) * H4 + hq] = acc;
}

// ---------------------------------------------------------------------------
// Kernel C: out = silu( silu(h @ W_skip + b_skip) + silu([h0,neigh] @ W_post + b_post) )
// 8 rows per block -> 256 blocks, 128 threads. 24 accumulators.
// ---------------------------------------------------------------------------
__global__ void __launch_bounds__(128) post_kernel(
    const float* __restrict__ h,
    const float* __restrict__ Wpost,
    const float* __restrict__ bpost,
    const float* __restrict__ Wskip,
    const float* __restrict__ bskip,
    float* __restrict__ out)
{
    __shared__ float h0s[8][Hv];
    __shared__ float nes[8][Hv];
    __shared__ float hsm[8][Hv];

    const int t = threadIdx.x;
    const int row0 = blockIdx.x * 8;

    const float4* h4 = (const float4*)h;
#pragma unroll
    for (int x = t; x < 8 * H4; x += 128) {
        ((float4*)h0s)[x] = ((const float4*)g_h0)[row0 * H4 + x];
        ((float4*)nes)[x] = ((const float4*)g_neigh)[row0 * H4 + x];
        ((float4*)hsm)[x] = h4[row0 * H4 + x];
    }
    __syncthreads();

    float accP[8], accS[8];
    const float bp = bpost[t];
    const float bs = bskip[t];
#pragma unroll
    for (int r = 0; r < 8; r++) { accP[r] = bp; accS[r] = bs; }

#pragma unroll 4
    for (int k = 0; k < Hv; k++) {
        const float w1 = Wpost[k * Hv + t];
        const float w2 = Wpost[(Hv + k) * Hv + t];
        const float w3 = Wskip[k * Hv + t];
#pragma unroll
        for (int r = 0; r < 8; r++) {
            accP[r] = fmaf(h0s[r][k], w1, accP[r]);
            accP[r] = fmaf(nes[r][k], w2, accP[r]);
            accS[r] = fmaf(hsm[r][k], w3, accS[r]);
        }
    }

#pragma unroll
    for (int r = 0; r < 8; r++)
        out[(row0 + r) * Hv + t] = silu_f(silu_f(accS[r]) + silu_f(accP[r]));
}

// ---------------------------------------------------------------------------
extern "C" void kernel_launch(void* const* d_in, const int* in_sizes, int n_in,
                              void* d_out, int out_size)
{
    const float* h     = (const float*)d_in[0];
    const float* e     = (const float*)d_in[1];
    const int*   graph = (const int*)  d_in[2];
    const float* Wpre  = (const float*)d_in[3];
    const float* bpre  = (const float*)d_in[4];
    const float* Wpost = (const float*)d_in[5];
    const float* bpost = (const float*)d_in[6];
    const float* Wskip = (const float*)d_in[7];
    const float* bskip = (const float*)d_in[8];
    float* out = (float*)d_out;

    pre_kernel<<<ROWS / 8, 128>>>(h, Wpre, bpre);
    agg_kernel<<<(Bv * Vv) / 8, 256>>>(e, graph);
    post_kernel<<<ROWS / 8, 128>>>(h, Wpost, bpost, Wskip, bskip, out);
}

// round 3
// speedup vs baseline: 2.1095x; 1.9086x over previous
#include <cuda_runtime.h>
#include <cstdint>

// Problem constants
#define Bv 8
#define Vv 256
#define Hv 128
#define ROWS (Bv*Vv)          // 2048
#define H4 (Hv/4)             // 32 float4 per row

// Intermediates (device globals; no allocation allowed)
__device__ float g_h0[ROWS*Hv];                 // silu(h @ W_pre + b_pre)
__device__ float g_sk[ROWS*Hv];                 // silu(h @ W_skip + b_skip)
__device__ float g_part[2*ROWS*Hv];             // neigh partial maxes (2 j-halves)

__device__ __forceinline__ float silu_f(float x) {
    return x * (1.0f / (1.0f + __expf(-x)));
}

__device__ __forceinline__ void cp16(uint32_t dst, const void* src) {
    asm volatile("cp.async.cg.shared.global [%0], [%1], 16;" :: "r"(dst), "l"(src));
}
__device__ __forceinline__ void cp_commit() {
    asm volatile("cp.async.commit_group;");
}

// ---------------------------------------------------------------------------
// Kernel A: h0 = silu(h @ W_pre + b_pre), sk = silu(h @ W_skip + b_skip)
// 256 blocks x 256 threads, 8 rows/block. W staged through smem in 32-k
// chunks, register-prefetched so LDG latency overlaps compute.
// thread: col = tid&127, rgroup = (tid>>7)*4 -> 4 rows each, 8 accumulators.
// ---------------------------------------------------------------------------
__global__ void __launch_bounds__(256) pre_kernel(
    const float* __restrict__ h,
    const float* __restrict__ Wpre,  const float* __restrict__ bpre,
    const float* __restrict__ Wskip, const float* __restrict__ bskip)
{
    __shared__ float hs[8][Hv];        // 4 KB
    __shared__ float WcA[32][Hv];      // 16 KB (W_pre chunk)
    __shared__ float WcB[32][Hv];      // 16 KB (W_skip chunk)

    const int tid  = threadIdx.x;
    const int col  = tid & 127;
    const int rg   = (tid >> 7) * 4;
    const int row0 = blockIdx.x * 8;

    // stage h rows: 8*32 = 256 float4, one per thread
    ((float4*)hs)[tid] = ((const float4*)h)[row0 * H4 + tid];

    const float4* WA = (const float4*)Wpre;
    const float4* WB = (const float4*)Wskip;

    // prefetch chunk 0 (32 k x 128 = 1024 float4 per matrix, 4/thread each)
    float4 pfA[4], pfB[4];
#pragma unroll
    for (int r = 0; r < 4; r++) {
        pfA[r] = WA[r * 256 + tid];
        pfB[r] = WB[r * 256 + tid];
    }

    float accA[4], accS[4];
    const float bA = bpre[col];
    const float bS = bskip[col];
#pragma unroll
    for (int rr = 0; rr < 4; rr++) { accA[rr] = bA; accS[rr] = bS; }

    for (int c = 0; c < 4; c++) {
        __syncthreads();                    // chunk buffer free (covers hs on c=0)
#pragma unroll
        for (int r = 0; r < 4; r++) {
            ((float4*)WcA)[r * 256 + tid] = pfA[r];
            ((float4*)WcB)[r * 256 + tid] = pfB[r];
        }
        __syncthreads();

        if (c < 3) {
#pragma unroll
            for (int r = 0; r < 4; r++) {
                pfA[r] = WA[(c + 1) * 1024 + r * 256 + tid];
                pfB[r] = WB[(c + 1) * 1024 + r * 256 + tid];
            }
        }

        const int kbase = c * 32;
#pragma unroll
        for (int kk = 0; kk < 32; kk += 4) {
            float wA[4], wB[4];
#pragma unroll
            for (int q = 0; q < 4; q++) {
                wA[q] = WcA[kk + q][col];
                wB[q] = WcB[kk + q][col];
            }
#pragma unroll
            for (int rr = 0; rr < 4; rr++) {
                float4 hv = *(const float4*)&hs[rg + rr][kbase + kk];
                accA[rr] = fmaf(hv.x, wA[0], accA[rr]);
                accA[rr] = fmaf(hv.y, wA[1], accA[rr]);
                accA[rr] = fmaf(hv.z, wA[2], accA[rr]);
                accA[rr] = fmaf(hv.w, wA[3], accA[rr]);
                accS[rr] = fmaf(hv.x, wB[0], accS[rr]);
                accS[rr] = fmaf(hv.y, wB[1], accS[rr]);
                accS[rr] = fmaf(hv.z, wB[2], accS[rr]);
                accS[rr] = fmaf(hv.w, wB[3], accS[rr]);
            }
        }
    }

#pragma unroll
    for (int rr = 0; rr < 4; rr++) {
        const int row = row0 + rg + rr;
        g_h0[row * Hv + col] = silu_f(accA[rr]);
        g_sk[row * Hv + col] = silu_f(accS[rr]);
    }
}

// ---------------------------------------------------------------------------
// Kernel B (dominant): partial neigh max over a 128-wide j-half.
// 512 blocks (b x 32 i-tiles x 2 j-halves) x 256 threads -> ALL resident
// (36 KB smem/block, no wave tail). h0 staged via cp.async double buffer.
// ---------------------------------------------------------------------------
__global__ void __launch_bounds__(256) agg_kernel(
    const float* __restrict__ e,
    const int*   __restrict__ graph)
{
    __shared__ float4 h0s[2][32 * H4];   // 2 x 16 KB
    __shared__ int    gsh[8][128];       // 4 KB

    const int tid  = threadIdx.x;
    const int hq   = tid & 31;           // float4 index in H
    const int isub = tid >> 5;           // 0..7
    const int b    = blockIdx.x >> 6;
    const int rem  = blockIdx.x & 63;
    const int i0   = (rem >> 1) * 8;
    const int jh   = rem & 1;
    const int j0   = jh * 128;
    const int i    = i0 + isub;

    // stage graph mask for this (i-tile, j-half): 1024 ints, 4/thread
#pragma unroll
    for (int x = tid; x < 8 * 128; x += 256) {
        gsh[x >> 7][x & 127] = graph[(b * Vv + i0 + (x >> 7)) * Vv + j0 + (x & 127)];
    }

    const float4* H0 = (const float4*)g_h0 + b * Vv * H4 + j0 * H4;
    const uint32_t sb0 = (uint32_t)__cvta_generic_to_shared(&h0s[0][0]);
    const uint32_t sb1 = (uint32_t)__cvta_generic_to_shared(&h0s[1][0]);

    // issue chunk c (32 j x 32 q = 1024 float4; 4 cp.async per thread)
    auto issue = [&](int c) {
        const uint32_t sb = (c & 1) ? sb1 : sb0;
#pragma unroll
        for (int r = 0; r < 4; r++) {
            const int x = r * 256 + tid;
            cp16(sb + x * 16, (const void*)(H0 + c * 1024 + x));
        }
        cp_commit();
    };
    issue(0);
    issue(1);

    const float4* Ep = (const float4*)e + ((size_t)(b * Vv + i) * Vv + j0) * H4 + hq;

    const float NEG_INF = __int_as_float(0xff800000);
    float4 acc = make_float4(NEG_INF, NEG_INF, NEG_INF, NEG_INF);

    for (int c = 0; c < 4; c++) {
        if (c == 3) asm volatile("cp.async.wait_group 0;");
        else        asm volatile("cp.async.wait_group 1;");
        __syncthreads();

        const float4* hb = h0s[c & 1];
        const int*    gm = &gsh[isub][c * 32];

#pragma unroll 8
        for (int jj = 0; jj < 32; jj++) {
            float4 ev = Ep[jj * H4];
            float4 hv = hb[jj * H4 + hq];
            if (gm[jj] != 0) { hv.x = 0.f; hv.y = 0.f; hv.z = 0.f; hv.w = 0.f; }
            acc.x = fmaxf(acc.x, ev.x * hv.x);
            acc.y = fmaxf(acc.y, ev.y * hv.y);
            acc.z = fmaxf(acc.z, ev.z * hv.z);
            acc.w = fmaxf(acc.w, ev.w * hv.w);
        }
        Ep += 32 * H4;

        __syncthreads();
        if (c + 2 < 4) issue(c + 2);
    }

    ((float4*)g_part)[((size_t)jh * ROWS + b * Vv + i) * H4 + hq] = acc;
}

// ---------------------------------------------------------------------------
// Kernel C: out = silu( sk + silu([h0,neigh] @ W_post + b_post) )
// 256 blocks x 256 threads, 8 rows/block. neigh = max of the two partials,
// folded in during staging. Same W-chunk pipeline as pre.
// ---------------------------------------------------------------------------
__global__ void __launch_bounds__(256) post_kernel(
    const float* __restrict__ Wpost, const float* __restrict__ bpost,
    float* __restrict__ out)
{
    __shared__ float h0s[8][Hv];       // 4 KB
    __shared__ float nes[8][Hv];       // 4 KB
    __shared__ float Wc1[32][Hv];      // 16 KB (W_post top half chunk)
    __shared__ float Wc2[32][Hv];      // 16 KB (W_post bottom half chunk)

    const int tid  = threadIdx.x;
    const int col  = tid & 127;
    const int rg   = (tid >> 7) * 4;
    const int row0 = blockIdx.x * 8;

    // stage h0 and neigh (= max of partials): 256 float4 each, 1/thread
    {
        const float4* gp = (const float4*)g_part;
        const int r = tid >> 5, q = tid & 31;
        ((float4*)h0s)[tid] = ((const float4*)g_h0)[row0 * H4 + tid];
        float4 p0 = gp[(row0 + r) * H4 + q];
        float4 p1 = gp[((size_t)ROWS + row0 + r) * H4 + q];
        float4 mx;
        mx.x = fmaxf(p0.x, p1.x); mx.y = fmaxf(p0.y, p1.y);
        mx.z = fmaxf(p0.z, p1.z); mx.w = fmaxf(p0.w, p1.w);
        ((float4*)nes)[tid] = mx;
    }

    const float4* W1 = (const float4*)Wpost;                 // rows [0,128)
    const float4* W2 = (const float4*)Wpost + Hv * H4;       // rows [128,256)

    float4 pf1[4], pf2[4];
#pragma unroll
    for (int r = 0; r < 4; r++) {
        pf1[r] = W1[r * 256 + tid];
        pf2[r] = W2[r * 256 + tid];
    }

    float accP[4];
    const float bP = bpost[col];
#pragma unroll
    for (int rr = 0; rr < 4; rr++) accP[rr] = bP;

    for (int c = 0; c < 4; c++) {
        __syncthreads();
#pragma unroll
        for (int r = 0; r < 4; r++) {
            ((float4*)Wc1)[r * 256 + tid] = pf1[r];
            ((float4*)Wc2)[r * 256 + tid] = pf2[r];
        }
        __syncthreads();

        if (c < 3) {
#pragma unroll
            for (int r = 0; r < 4; r++) {
                pf1[r] = W1[(c + 1) * 1024 + r * 256 + tid];
                pf2[r] = W2[(c + 1) * 1024 + r * 256 + tid];
            }
        }

        const int kbase = c * 32;
#pragma unroll
        for (int kk = 0; kk < 32; kk += 4) {
            float w1[4], w2[4];
#pragma unroll
            for (int q = 0; q < 4; q++) {
                w1[q] = Wc1[kk + q][col];
                w2[q] = Wc2[kk + q][col];
            }
#pragma unroll
            for (int rr = 0; rr < 4; rr++) {
                float4 av = *(const float4*)&h0s[rg + rr][kbase + kk];
                float4 bv = *(const float4*)&nes[rg + rr][kbase + kk];
                accP[rr] = fmaf(av.x, w1[0], accP[rr]);
                accP[rr] = fmaf(av.y, w1[1], accP[rr]);
                accP[rr] = fmaf(av.z, w1[2], accP[rr]);
                accP[rr] = fmaf(av.w, w1[3], accP[rr]);
                accP[rr] = fmaf(bv.x, w2[0], accP[rr]);
                accP[rr] = fmaf(bv.y, w2[1], accP[rr]);
                accP[rr] = fmaf(bv.z, w2[2], accP[rr]);
                accP[rr] = fmaf(bv.w, w2[3], accP[rr]);
            }
        }
    }

#pragma unroll
    for (int rr = 0; rr < 4; rr++) {
        const int row = row0 + rg + rr;
        out[row * Hv + col] = silu_f(g_sk[row * Hv + col] + silu_f(accP[rr]));
    }
}

// ---------------------------------------------------------------------------
extern "C" void kernel_launch(void* const* d_in, const int* in_sizes, int n_in,
                              void* d_out, int out_size)
{
    const float* h     = (const float*)d_in[0];
    const float* e     = (const float*)d_in[1];
    const int*   graph = (const int*)  d_in[2];
    const float* Wpre  = (const float*)d_in[3];
    const float* bpre  = (const float*)d_in[4];
    const float* Wpost = (const float*)d_in[5];
    const float* bpost = (const float*)d_in[6];
    const float* Wskip = (const float*)d_in[7];
    const float* bskip = (const float*)d_in[8];
    float* out = (float*)d_out;

    pre_kernel<<<ROWS / 8, 256>>>(h, Wpre, bpre, Wskip, bskip);
    agg_kernel<<<(ROWS / 8) * 2, 256>>>(e, graph);
    post_kernel<<<ROWS / 8, 256>>>(Wpost, bpost, out);
}